// round 6
// baseline (speedup 1.0000x reference)
#include <cuda_runtime.h>
#include <cuda_fp16.h>
#include <cstdint>

// Problem dims
#define TOKENS 8192
#define IN_F   4096
#define OUT_F  4096
#define GROUPS (OUT_F * IN_F / 64)   // 262144
#define HALF_G (GROUPS / 2)          // 131072
#define PACKED (HALF_G * 64)         // 8388608

// Scratch: fp16 copies of x and dequantized W (device globals — no allocs)
__device__ __align__(1024) __half g_X16[(size_t)TOKENS * IN_F];  // 64 MB
__device__ __align__(1024) __half g_W16[(size_t)OUT_F * IN_F];   // 32 MB

// ============================================================================
// Prep kernel 1: x fp32 -> fp16
// ============================================================================
__global__ void cvt_x_kernel(const float4* __restrict__ x, uint2* __restrict__ o, int n4) {
    for (int i = blockIdx.x * blockDim.x + threadIdx.x; i < n4;
         i += gridDim.x * blockDim.x) {
        float4 v = x[i];
        union { __half2 h; unsigned u; } c0, c1;
        c0.h = __floats2half2_rn(v.x, v.y);
        c1.h = __floats2half2_rn(v.z, v.w);
        uint2 u; u.x = c0.u; u.y = c1.u;
        o[i] = u;
    }
}

// ============================================================================
// Prep kernel 2: 4-bit dequant -> fp16 W [OUT_F, IN_F] row-major (K contiguous)
// hi nibble -> groups [0, G/2), lo nibble -> groups [G/2, G).
// Flat element index for (group g, lane j) is g*64+j = packed index.
// ============================================================================
__global__ void deq_w_kernel(const int* __restrict__ Wq, const float* __restrict__ scale,
                             const float* __restrict__ zero, __half* __restrict__ w16) {
    for (int i = blockIdx.x * blockDim.x + threadIdx.x; i < PACKED;
         i += gridDim.x * blockDim.x) {
        int q = Wq[i];
        int g = i >> 6;
        float s1 = __ldg(scale + g),          z1 = __ldg(zero + g);
        float s2 = __ldg(scale + g + HALF_G), z2 = __ldg(zero + g + HALF_G);
        w16[i]          = __float2half_rn(((float)((q >> 4) & 0xF) - z1) * s1);
        w16[i + PACKED] = __float2half_rn(((float)(q & 0xF)        - z2) * s2);
    }
}

// ============================================================================
// GEMM: out[8192,4096] = X16 @ W16^T + bias   (fp16 inputs, fp32 accumulate)
// Ampere-style: cp.async multistage + ldmatrix + mma.sync.m16n8k16
// CTA tile 128(M) x 128(N) x 32(K), 4 stages, 256 threads (2x4 warp grid).
// SMEM rows padded to 40 halves (80B): ldmatrix phases are bank-conflict-free
// (row stride of 20 banks -> starts {0,20,8,28,16,4,24,12}, disjoint spans).
// ============================================================================
#define BM 128
#define BN 128
#define BK 32
#define STAGES 4
#define ROW_HALFS 40                       // 32 data + 8 pad
#define ROW_BYTES (ROW_HALFS * 2)          // 80
#define TILE_BYTES (BM * ROW_BYTES)        // 10240
#define STAGE_BYTES (2 * TILE_BYTES)       // 20480 (A then B)
#define SMEM_TOTAL (STAGES * STAGE_BYTES)  // 81920

__device__ __forceinline__ uint32_t smem_u32(const void* p) {
    uint32_t a;
    asm("{ .reg .u64 t; cvta.to.shared.u64 t, %1; cvt.u32.u64 %0, t; }"
        : "=r"(a) : "l"(p));
    return a;
}

#define CP_ASYNC_16(dst_u32, src_ptr) \
    asm volatile("cp.async.cg.shared.global [%0], [%1], 16;" \
        :: "r"(dst_u32), "l"(src_ptr) : "memory")
#define CP_COMMIT() asm volatile("cp.async.commit_group;" ::: "memory")
#define CP_WAIT(n)  asm volatile("cp.async.wait_group %0;" :: "n"(n) : "memory")

#define LDSM_X4(r0, r1, r2, r3, addr) \
    asm volatile("ldmatrix.sync.aligned.m8n8.x4.shared.b16 {%0,%1,%2,%3}, [%4];" \
        : "=r"(r0), "=r"(r1), "=r"(r2), "=r"(r3) : "r"(addr))

#define MMA_16816(c0, c1, c2, c3, a0, a1, a2, a3, b0, b1) \
    asm volatile("mma.sync.aligned.m16n8k16.row.col.f32.f16.f16.f32 " \
        "{%0,%1,%2,%3}, {%4,%5,%6,%7}, {%8,%9}, {%0,%1,%2,%3};" \
        : "+f"(c0), "+f"(c1), "+f"(c2), "+f"(c3) \
        : "r"(a0), "r"(a1), "r"(a2), "r"(a3), "r"(b0), "r"(b1))

__global__ void __launch_bounds__(256, 2)
gemm_f16_kernel(const __half* __restrict__ X16, const __half* __restrict__ W16,
                const float* __restrict__ bias, float* __restrict__ out) {
    extern __shared__ __align__(128) char smem[];
    const uint32_t sb = smem_u32(smem);
    const int tid = threadIdx.x;
    const int wid = tid >> 5, lid = tid & 31;
    const int warp_m = wid & 1;        // 0..1, 64 rows each
    const int warp_n = wid >> 1;       // 0..3, 32 cols each
    const int bn = blockIdx.x, bm = blockIdx.y;

    // ---- per-thread load slots: 2 x 16B vectors per tile per operand ----
    // vector v covers (row = v/4, col8 = v%4) of a [128][32] fp16 tile
    const int v0 = tid, v1 = tid + 256;
    const int a_r0 = v0 >> 2, a_c0 = v0 & 3;
    const int a_r1 = v1 >> 2, a_c1 = v1 & 3;
    const __half* gA0 = X16 + (size_t)(bm * BM + a_r0) * IN_F + a_c0 * 8;
    const __half* gA1 = X16 + (size_t)(bm * BM + a_r1) * IN_F + a_c1 * 8;
    const __half* gB0 = W16 + (size_t)(bn * BN + a_r0) * IN_F + a_c0 * 8;
    const __half* gB1 = W16 + (size_t)(bn * BN + a_r1) * IN_F + a_c1 * 8;
    const uint32_t sA0 = a_r0 * ROW_BYTES + a_c0 * 16;
    const uint32_t sA1 = a_r1 * ROW_BYTES + a_c1 * 16;

    float c[4][4][4];
    #pragma unroll
    for (int i = 0; i < 4; i++)
        #pragma unroll
        for (int j = 0; j < 4; j++)
            c[i][j][0] = c[i][j][1] = c[i][j][2] = c[i][j][3] = 0.f;

    const int NK = IN_F / BK;  // 128

    // ---- prologue: fill stages 0..STAGES-2 ----
    #pragma unroll
    for (int s = 0; s < STAGES - 1; s++) {
        uint32_t st = sb + s * STAGE_BYTES;
        CP_ASYNC_16(st + sA0,              gA0 + s * BK);
        CP_ASYNC_16(st + sA1,              gA1 + s * BK);
        CP_ASYNC_16(st + TILE_BYTES + sA0, gB0 + s * BK);
        CP_ASYNC_16(st + TILE_BYTES + sA1, gB1 + s * BK);
        CP_COMMIT();
    }

    // ldmatrix lane addressing (computed once)
    const int lm_row  = lid & 15;          // A: row within m16 tile
    const int lm_half = lid >> 4;          // A: k-half (0/1) -> +16B
    const int lb_j    = lid >> 3;          // B: 8x8 tile index 0..3
    const int lb_nin  = ((lb_j >> 1) << 3) + (lid & 7);  // n within n16
    const int lb_koff = (lb_j & 1) * 16;   // B: k-half byte offset

    for (int kt = 0; kt < NK; kt++) {
        CP_WAIT(2);
        __syncthreads();

        // prefetch tile kt+3 into the stage last read at iter kt-1
        if (kt + STAGES - 1 < NK) {
            const int kn = kt + STAGES - 1;
            uint32_t st = sb + (kn & (STAGES - 1)) * STAGE_BYTES;
            CP_ASYNC_16(st + sA0,              gA0 + kn * BK);
            CP_ASYNC_16(st + sA1,              gA1 + kn * BK);
            CP_ASYNC_16(st + TILE_BYTES + sA0, gB0 + kn * BK);
            CP_ASYNC_16(st + TILE_BYTES + sA1, gB1 + kn * BK);
        }
        CP_COMMIT();

        // ---- compute on stage kt ----
        const uint32_t stA = sb + (kt & (STAGES - 1)) * STAGE_BYTES
                           + (warp_m * 64) * ROW_BYTES;
        const uint32_t stB = sb + (kt & (STAGES - 1)) * STAGE_BYTES + TILE_BYTES
                           + (warp_n * 32) * ROW_BYTES;

        #pragma unroll
        for (int kk = 0; kk < 2; kk++) {   // two k16 steps per BK=32
            uint32_t a[4][4];
            #pragma unroll
            for (int mi = 0; mi < 4; mi++) {
                uint32_t ad = stA + (mi * 16 + lm_row) * ROW_BYTES
                            + kk * 32 + lm_half * 16;
                LDSM_X4(a[mi][0], a[mi][1], a[mi][2], a[mi][3], ad);
            }
            uint32_t b[4][2];
            #pragma unroll
            for (int nj = 0; nj < 2; nj++) {
                uint32_t bd = stB + (nj * 16 + lb_nin) * ROW_BYTES
                            + kk * 32 + lb_koff;
                LDSM_X4(b[2*nj][0], b[2*nj][1], b[2*nj+1][0], b[2*nj+1][1], bd);
            }
            #pragma unroll
            for (int mi = 0; mi < 4; mi++)
                #pragma unroll
                for (int nf = 0; nf < 4; nf++)
                    MMA_16816(c[mi][nf][0], c[mi][nf][1], c[mi][nf][2], c[mi][nf][3],
                              a[mi][0], a[mi][1], a[mi][2], a[mi][3],
                              b[nf][0], b[nf][1]);
        }
    }

    // ---- epilogue: C fragment -> gmem + bias ----
    // lane l: rows (l/4, l/4+8), cols (2*(l%4), +1) within each m16n8 frag
    const int er = lid >> 2, ec = (lid & 3) * 2;
    #pragma unroll
    for (int mi = 0; mi < 4; mi++) {
        const int gm0 = bm * BM + warp_m * 64 + mi * 16 + er;
        #pragma unroll
        for (int nf = 0; nf < 4; nf++) {
            const int gn = bn * BN + warp_n * 32 + nf * 8 + ec;
            const float b0 = __ldg(bias + gn), b1 = __ldg(bias + gn + 1);
            float2 v0 = {c[mi][nf][0] + b0, c[mi][nf][1] + b1};
            float2 v1 = {c[mi][nf][2] + b0, c[mi][nf][3] + b1};
            *reinterpret_cast<float2*>(out + (size_t)gm0 * OUT_F + gn) = v0;
            *reinterpret_cast<float2*>(out + (size_t)(gm0 + 8) * OUT_F + gn) = v1;
        }
    }
}

// ============================================================================
// Host launch
// ============================================================================
extern "C" void kernel_launch(void* const* d_in, const int* in_sizes, int n_in,
                              void* d_out, int out_size) {
    (void)in_sizes; (void)n_in; (void)out_size;
    const float* x     = (const float*)d_in[0];
    const int*   Wq    = (const int*)d_in[1];
    const float* scale = (const float*)d_in[2];
    const float* zero  = (const float*)d_in[3];
    const float* bias  = (const float*)d_in[4];
    float* out = (float*)d_out;

    void *pX = nullptr, *pW = nullptr;
    cudaGetSymbolAddress(&pX, g_X16);
    cudaGetSymbolAddress(&pW, g_W16);

    cvt_x_kernel<<<4096, 256>>>((const float4*)x, (uint2*)pX, TOKENS * IN_F / 4);
    deq_w_kernel<<<4096, 256>>>(Wq, scale, zero, (__half*)pW);

    cudaFuncSetAttribute(gemm_f16_kernel, cudaFuncAttributeMaxDynamicSharedMemorySize,
                         SMEM_TOTAL);
    dim3 grid(OUT_F / BN, TOKENS / BM);   // (32, 64) = 2048 CTAs
    gemm_f16_kernel<<<grid, 256, SMEM_TOTAL>>>((const __half*)pX, (const __half*)pW,
                                               bias, out);
}

// round 9
// speedup vs baseline: 1.0003x; 1.0003x over previous
#include <cuda_runtime.h>
#include <cuda_fp16.h>
#include <cstdint>

// Problem dims
#define TOKENS 8192
#define IN_F   4096
#define OUT_F  4096
#define GROUPS (OUT_F * IN_F / 64)   // 262144
#define HALF_G (GROUPS / 2)          // 131072
#define PACKED (HALF_G * 64)         // 8388608

// Scratch: fp16 copies of x and dequantized W (device globals — no allocs)
__device__ __align__(1024) __half g_X16[(size_t)TOKENS * IN_F];  // 64 MB
__device__ __align__(1024) __half g_W16[(size_t)OUT_F * IN_F];   // 32 MB

// ============================================================================
// Prep kernel 1: x fp32 -> fp16
// ============================================================================
__global__ void cvt_x_kernel(const float4* __restrict__ x, uint2* __restrict__ o, int n4) {
    for (int i = blockIdx.x * blockDim.x + threadIdx.x; i < n4;
         i += gridDim.x * blockDim.x) {
        float4 v = x[i];
        union { __half2 h; unsigned u; } c0, c1;
        c0.h = __floats2half2_rn(v.x, v.y);
        c1.h = __floats2half2_rn(v.z, v.w);
        uint2 u; u.x = c0.u; u.y = c1.u;
        o[i] = u;
    }
}

// ============================================================================
// Prep kernel 2: 4-bit dequant -> fp16 W [OUT_F, IN_F] row-major (K contiguous)
// ============================================================================
__global__ void deq_w_kernel(const int* __restrict__ Wq, const float* __restrict__ scale,
                             const float* __restrict__ zero, __half* __restrict__ w16) {
    for (int i = blockIdx.x * blockDim.x + threadIdx.x; i < PACKED;
         i += gridDim.x * blockDim.x) {
        int q = Wq[i];
        int g = i >> 6;
        float s1 = __ldg(scale + g),          z1 = __ldg(zero + g);
        float s2 = __ldg(scale + g + HALF_G), z2 = __ldg(zero + g + HALF_G);
        w16[i]          = __float2half_rn(((float)((q >> 4) & 0xF) - z1) * s1);
        w16[i + PACKED] = __float2half_rn(((float)(q & 0xF)        - z2) * s2);
    }
}

// ============================================================================
// GEMM: out[8192,4096] = X16 @ W16^T + bias   (fp16 in, fp32 accum)
// CTA tile 256(M) x 128(N) x 64(K), 3 cp.async stages, 256 threads.
// Warp grid 4(m) x 2(n): each warp owns 64x64 (4 m16-frags x 8 n8-frags).
// SMEM rows padded to 72 halves (144B): row stride = 36 banks = 4 (mod 32),
// so each 8-row ldmatrix phase hits 8 disjoint 4-bank spans -> conflict-free.
// ============================================================================
#define BM 256
#define BN 128
#define BK 64
#define STAGES 3
#define ROW_HALFS 72                          // 64 data + 8 pad
#define ROW_BYTES (ROW_HALFS * 2)             // 144
#define A_TILE_BYTES (BM * ROW_BYTES)         // 36864
#define B_TILE_BYTES (BN * ROW_BYTES)         // 18432
#define STAGE_BYTES (A_TILE_BYTES + B_TILE_BYTES)   // 55296
#define SMEM_TOTAL (STAGES * STAGE_BYTES)     // 165888

__device__ __forceinline__ uint32_t smem_u32(const void* p) {
    uint32_t a;
    asm("{ .reg .u64 t; cvta.to.shared.u64 t, %1; cvt.u32.u64 %0, t; }"
        : "=r"(a) : "l"(p));
    return a;
}

#define CP_ASYNC_16(dst_u32, src_ptr) \
    asm volatile("cp.async.cg.shared.global [%0], [%1], 16;" \
        :: "r"(dst_u32), "l"(src_ptr) : "memory")
#define CP_COMMIT() asm volatile("cp.async.commit_group;" ::: "memory")
#define CP_WAIT(n)  asm volatile("cp.async.wait_group %0;" :: "n"(n) : "memory")

#define LDSM_X4(r0, r1, r2, r3, addr) \
    asm volatile("ldmatrix.sync.aligned.m8n8.x4.shared.b16 {%0,%1,%2,%3}, [%4];" \
        : "=r"(r0), "=r"(r1), "=r"(r2), "=r"(r3) : "r"(addr))

#define MMA_16816(c0, c1, c2, c3, a0, a1, a2, a3, b0, b1) \
    asm volatile("mma.sync.aligned.m16n8k16.row.col.f32.f16.f16.f32 " \
        "{%0,%1,%2,%3}, {%4,%5,%6,%7}, {%8,%9}, {%0,%1,%2,%3};" \
        : "+f"(c0), "+f"(c1), "+f"(c2), "+f"(c3) \
        : "r"(a0), "r"(a1), "r"(a2), "r"(a3), "r"(b0), "r"(b1))

__global__ void __launch_bounds__(256, 1)
gemm_f16_kernel(const __half* __restrict__ X16, const __half* __restrict__ W16,
                const float* __restrict__ bias, float* __restrict__ out) {
    extern __shared__ __align__(128) char smem[];
    const uint32_t sb = smem_u32(smem);
    const int tid = threadIdx.x;
    const int wid = tid >> 5, lid = tid & 31;
    const int warp_m = wid & 3;        // 0..3 -> 64 rows each
    const int warp_n = wid >> 2;       // 0..1 -> 64 cols each
    const int bn = blockIdx.x, bm = blockIdx.y;

    // ---- cp.async slots ----
    // A tile [256][64]: 8 vectors/row of 16B -> 2048 vectors, 8 per thread.
    // B tile [128][64]: 1024 vectors, 4 per thread.
    // vector v: row = v>>3, col8 = v&7.
    const __half* gAbase = X16 + (size_t)(bm * BM) * IN_F;
    const __half* gBbase = W16 + (size_t)(bn * BN) * IN_F;

    uint32_t sAoff[8], sBoff[4];
    const __half* gA[8];
    const __half* gB[4];
    #pragma unroll
    for (int i = 0; i < 8; i++) {
        int v = tid + 256 * i;
        int r = v >> 3, c8 = v & 7;
        sAoff[i] = r * ROW_BYTES + c8 * 16;
        gA[i] = gAbase + (size_t)r * IN_F + c8 * 8;
    }
    #pragma unroll
    for (int i = 0; i < 4; i++) {
        int v = tid + 256 * i;
        int r = v >> 3, c8 = v & 7;
        sBoff[i] = r * ROW_BYTES + c8 * 16;
        gB[i] = gBbase + (size_t)r * IN_F + c8 * 8;
    }

    float c[4][8][4];
    #pragma unroll
    for (int mi = 0; mi < 4; mi++)
        #pragma unroll
        for (int nf = 0; nf < 8; nf++)
            c[mi][nf][0] = c[mi][nf][1] = c[mi][nf][2] = c[mi][nf][3] = 0.f;

    const int NK = IN_F / BK;  // 64

    // ---- prologue: fill stages 0..STAGES-2 ----
    #pragma unroll
    for (int s = 0; s < STAGES - 1; s++) {
        uint32_t st = sb + s * STAGE_BYTES;
        #pragma unroll
        for (int i = 0; i < 8; i++) CP_ASYNC_16(st + sAoff[i], gA[i] + s * BK);
        #pragma unroll
        for (int i = 0; i < 4; i++)
            CP_ASYNC_16(st + A_TILE_BYTES + sBoff[i], gB[i] + s * BK);
        CP_COMMIT();
    }

    // ldmatrix lane addressing
    const int lm_row  = lid & 15;          // A: row within m16 tile
    const int lm_half = lid >> 4;          // A: k-half -> +16B
    const int lb_j    = lid >> 3;          // B: 8x8 tile index 0..3
    const int lb_nin  = ((lb_j >> 1) << 3) + (lid & 7);
    const int lb_koff = (lb_j & 1) * 16;

    int st_idx = 0;
    for (int kt = 0; kt < NK; kt++) {
        CP_WAIT(1);
        __syncthreads();

        // prefetch tile kt+2 into the stage consumed at iter kt-1
        if (kt + STAGES - 1 < NK) {
            const int kn = kt + STAGES - 1;
            int si = st_idx + 2; if (si >= STAGES) si -= STAGES;
            uint32_t st = sb + si * STAGE_BYTES;
            #pragma unroll
            for (int i = 0; i < 8; i++) CP_ASYNC_16(st + sAoff[i], gA[i] + kn * BK);
            #pragma unroll
            for (int i = 0; i < 4; i++)
                CP_ASYNC_16(st + A_TILE_BYTES + sBoff[i], gB[i] + kn * BK);
        }
        CP_COMMIT();

        // ---- compute on stage st_idx ----
        const uint32_t stA = sb + st_idx * STAGE_BYTES + (warp_m * 64) * ROW_BYTES;
        const uint32_t stB = sb + st_idx * STAGE_BYTES + A_TILE_BYTES
                           + (warp_n * 64) * ROW_BYTES;

        #pragma unroll
        for (int kk = 0; kk < 4; kk++) {   // four k16 steps per BK=64
            uint32_t a[4][4];
            #pragma unroll
            for (int mi = 0; mi < 4; mi++) {
                uint32_t ad = stA + (mi * 16 + lm_row) * ROW_BYTES
                            + kk * 32 + lm_half * 16;
                LDSM_X4(a[mi][0], a[mi][1], a[mi][2], a[mi][3], ad);
            }
            uint32_t b[8][2];
            #pragma unroll
            for (int nj = 0; nj < 4; nj++) {   // four n16 groups = 64 cols
                uint32_t bd = stB + (nj * 16 + lb_nin) * ROW_BYTES
                            + kk * 32 + lb_koff;
                LDSM_X4(b[2*nj][0], b[2*nj][1], b[2*nj+1][0], b[2*nj+1][1], bd);
            }
            #pragma unroll
            for (int mi = 0; mi < 4; mi++)
                #pragma unroll
                for (int nf = 0; nf < 8; nf++)
                    MMA_16816(c[mi][nf][0], c[mi][nf][1], c[mi][nf][2], c[mi][nf][3],
                              a[mi][0], a[mi][1], a[mi][2], a[mi][3],
                              b[nf][0], b[nf][1]);
        }
        if (++st_idx == STAGES) st_idx = 0;
    }

    // ---- epilogue ----
    const int er = lid >> 2, ec = (lid & 3) * 2;
    #pragma unroll
    for (int mi = 0; mi < 4; mi++) {
        const int gm0 = bm * BM + warp_m * 64 + mi * 16 + er;
        #pragma unroll
        for (int nf = 0; nf < 8; nf++) {
            const int gn = bn * BN + warp_n * 64 + nf * 8 + ec;
            const float b0 = __ldg(bias + gn), b1 = __ldg(bias + gn + 1);
            float2 v0 = {c[mi][nf][0] + b0, c[mi][nf][1] + b1};
            float2 v1 = {c[mi][nf][2] + b0, c[mi][nf][3] + b1};
            *reinterpret_cast<float2*>(out + (size_t)gm0 * OUT_F + gn) = v0;
            *reinterpret_cast<float2*>(out + (size_t)(gm0 + 8) * OUT_F + gn) = v1;
        }
    }
}

// ============================================================================
// Host launch
// ============================================================================
extern "C" void kernel_launch(void* const* d_in, const int* in_sizes, int n_in,
                              void* d_out, int out_size) {
    (void)in_sizes; (void)n_in; (void)out_size;
    const float* x     = (const float*)d_in[0];
    const int*   Wq    = (const int*)d_in[1];
    const float* scale = (const float*)d_in[2];
    const float* zero  = (const float*)d_in[3];
    const float* bias  = (const float*)d_in[4];
    float* out = (float*)d_out;

    void *pX = nullptr, *pW = nullptr;
    cudaGetSymbolAddress(&pX, g_X16);
    cudaGetSymbolAddress(&pW, g_W16);

    cvt_x_kernel<<<4096, 256>>>((const float4*)x, (uint2*)pX, TOKENS * IN_F / 4);
    deq_w_kernel<<<4096, 256>>>(Wq, scale, zero, (__half*)pW);

    cudaFuncSetAttribute(gemm_f16_kernel, cudaFuncAttributeMaxDynamicSharedMemorySize,
                         SMEM_TOTAL);
    dim3 grid(OUT_F / BN, TOKENS / BM);   // (32, 32) = 1024 CTAs
    gemm_f16_kernel<<<grid, 256, SMEM_TOTAL>>>((const __half*)pX, (const __half*)pW,
                                               bias, out);
}